// round 8
// baseline (speedup 1.0000x reference)
#include <cuda_runtime.h>
#include <cuda_fp16.h>
#include <math.h>
#include <stdint.h>

#define BATCH 2
#define SEQ   4096
#define DIM   128
#define NTOK  (BATCH * SEQ)
#define SCALE 0.125f   // 64^-0.5
#define NSPLIT 2
#define JT_PER_SPLIT (64 / NSPLIT)

// ---------------- device scratch ----------------
__device__ float  g_W[640 * 128];
__device__ float  g_q[NTOK * DIM];            // reused as h1 after flash
__device__ __half g_kh[NTOK * DIM];
__device__ __half g_kl[NTOK * DIM];
__device__ __half g_vh[(size_t)DIM * NTOK];   // V fp16, transposed [d][tok]
__device__ float  g_sq[NTOK];
__device__ __half g_dist[(size_t)BATCH * SEQ * SEQ];
__device__ double g_sum_spe;
__device__ float  g_inv2s2_spe;
__device__ float  g_spa[64 * 64];
__device__ float  g_attn[NTOK * DIM];
__device__ float  g_po[NSPLIT][NTOK * DIM];   // unnormalized partial outputs
__device__ float2 g_pml[NSPLIT][NTOK * 2];    // (m, l) per row per head

// ---------------- helpers ----------------
__device__ __forceinline__ uint32_t f2tf(float f) {
    uint32_t r; asm("cvt.rna.tf32.f32 %0, %1;" : "=r"(r) : "f"(f)); return r;
}
__device__ __forceinline__ void mma8(float* c, const uint32_t* a, uint32_t b0, uint32_t b1) {
    asm volatile("mma.sync.aligned.m16n8k8.row.col.f32.tf32.tf32.f32 "
                 "{%0,%1,%2,%3},{%4,%5,%6,%7},{%8,%9},{%0,%1,%2,%3};"
                 : "+f"(c[0]), "+f"(c[1]), "+f"(c[2]), "+f"(c[3])
                 : "r"(a[0]), "r"(a[1]), "r"(a[2]), "r"(a[3]), "r"(b0), "r"(b1));
}
__device__ __forceinline__ void mma16(float* c, const uint32_t* a, uint32_t b0, uint32_t b1) {
    asm volatile("mma.sync.aligned.m16n8k16.row.col.f32.f16.f16.f32 "
                 "{%0,%1,%2,%3},{%4,%5,%6,%7},{%8,%9},{%0,%1,%2,%3};"
                 : "+f"(c[0]), "+f"(c[1]), "+f"(c[2]), "+f"(c[3])
                 : "r"(a[0]), "r"(a[1]), "r"(a[2]), "r"(a[3]), "r"(b0), "r"(b1));
}

// ---------------- init ----------------
__global__ void k_init() { g_sum_spe = 0.0; }

// ---------------- weight norm ----------------
__global__ void k_weights(const float* __restrict__ vq, const float* __restrict__ gq,
                          const float* __restrict__ v1, const float* __restrict__ g1,
                          const float* __restrict__ v2, const float* __restrict__ g2) {
    int r = blockIdx.x, t = threadIdx.x;
    const float* v; float g;
    if (r < 384)      { v = vq + r * 128;        g = gq[r]; }
    else if (r < 512) { v = v1 + (r - 384) * 128; g = g1[r - 384]; }
    else              { v = v2 + (r - 512) * 128; g = g2[r - 512]; }
    float val = v[t];
    float ss = val * val;
    #pragma unroll
    for (int o = 16; o; o >>= 1) ss += __shfl_xor_sync(0xffffffffu, ss, o);
    __shared__ float ws[4];
    if ((t & 31) == 0) ws[t >> 5] = ss;
    __syncthreads();
    float tot = ws[0] + ws[1] + ws[2] + ws[3];
    g_W[r * 128 + t] = val * (g / sqrtf(tot));
}

// ---------------- per-token ||x||^2 ----------------
__global__ void k_sq(const float* __restrict__ x) {
    int token = blockIdx.x * 8 + (threadIdx.x >> 5);
    int lane  = threadIdx.x & 31;
    const float4* xp = (const float4*)(x + token * 128);
    float4 a = xp[lane];
    float ss = a.x * a.x + a.y * a.y + a.z * a.z + a.w * a.w;
    #pragma unroll
    for (int o = 16; o; o >>= 1) ss += __shfl_xor_sync(0xffffffffu, ss, o);
    if (lane == 0) g_sq[token] = ss;
}

// ---------------- tiled projection GEMM (scalar fp32, exact) ----------------
__global__ void __launch_bounds__(256) k_gemm64(const float* __restrict__ A,
                                                const float* __restrict__ Wrows,
                                                const float* __restrict__ bias,
                                                float* __restrict__ out, int mode) {
    extern __shared__ float sm[];
    float* aT = sm;
    float* wT = sm + 128 * 68;
    int c0 = blockIdx.x * 64;
    int t0 = blockIdx.y * 64;
    int tid = threadIdx.x;
    for (int idx = tid; idx < 64 * 128; idx += 256) {
        int r = idx >> 7, k = idx & 127;
        aT[k * 68 + r] = A[(t0 + r) * 128 + k];
        wT[k * 68 + r] = Wrows[(c0 + r) * 128 + k];
    }
    __syncthreads();
    int ty = tid >> 4, tx = tid & 15;
    float acc[4][4] = {};
    #pragma unroll 4
    for (int k = 0; k < 128; k++) {
        float4 av = *(const float4*)&aT[k * 68 + 4 * ty];
        float4 bv = *(const float4*)&wT[k * 68 + 4 * tx];
        float a[4] = {av.x, av.y, av.z, av.w};
        float c[4] = {bv.x, bv.y, bv.z, bv.w};
        #pragma unroll
        for (int i = 0; i < 4; i++)
            #pragma unroll
            for (int j = 0; j < 4; j++) acc[i][j] = fmaf(a[i], c[j], acc[i][j]);
    }
    #pragma unroll
    for (int i = 0; i < 4; i++) {
        int token = t0 + 4 * ty + i;
        #pragma unroll
        for (int j = 0; j < 4; j++) {
            int c = c0 + 4 * tx + j;
            float val = acc[i][j] + __ldg(&bias[c]);
            if (mode == 0) {
                if (c < 128) {
                    g_q[token * 128 + c] = val;
                } else if (c < 256) {
                    int d = c - 128;
                    __half hi = __float2half_rn(val);
                    __half lo = __float2half_rn(val - __half2float(hi));
                    g_kh[token * 128 + d] = hi;
                    g_kl[token * 128 + d] = lo;
                } else {
                    int d = c - 256;
                    g_vh[(size_t)d * NTOK + token] = __float2half_rn(val);
                }
            } else if (mode == 1) {
                g_q[token * 128 + c] = 0.5f * val * (1.0f + erff(val * 0.70710678118654752f));
            } else {
                out[token * 128 + c] = val;
            }
        }
    }
}

// ---------------- pairwise distance via tf32 MMA ----------------
__global__ void __launch_bounds__(256) k_dist(const float* __restrict__ x) {
    extern __shared__ float sm[];
    float* xi = sm;              // [128][132], tf32-rounded
    float* xj = sm + 128 * 132;
    int b = blockIdx.z, i0 = blockIdx.y * 128, j0 = blockIdx.x * 128;
    int tid = threadIdx.x;
    for (int fi = tid; fi < 4096; fi += 256) {
        int r = fi >> 5, c4 = (fi & 31) * 4;
        float4 a = *(const float4*)&x[(size_t)(b * SEQ + i0 + r) * 128 + c4];
        float4 bb = *(const float4*)&x[(size_t)(b * SEQ + j0 + r) * 128 + c4];
        a.x = __uint_as_float(f2tf(a.x)); a.y = __uint_as_float(f2tf(a.y));
        a.z = __uint_as_float(f2tf(a.z)); a.w = __uint_as_float(f2tf(a.w));
        bb.x = __uint_as_float(f2tf(bb.x)); bb.y = __uint_as_float(f2tf(bb.y));
        bb.z = __uint_as_float(f2tf(bb.z)); bb.w = __uint_as_float(f2tf(bb.w));
        *(float4*)&xi[r * 132 + c4] = a;
        *(float4*)&xj[r * 132 + c4] = bb;
    }
    __syncthreads();
    int lane = tid & 31, w = tid >> 5;
    int wr = w >> 1, wc = w & 1;
    int g = lane >> 2, t = lane & 3;
    float c[2][8][4] = {};
    #pragma unroll 1
    for (int ks = 0; ks < 16; ks++) {
        uint32_t A[2][4];
        #pragma unroll
        for (int mt = 0; mt < 2; mt++)
            #pragma unroll
            for (int e = 0; e < 4; e++)
                A[mt][e] = __float_as_uint(xi[(32 * wr + 16 * mt + g + 8 * (e & 1)) * 132 + 8 * ks + t + 4 * (e >> 1)]);
        #pragma unroll
        for (int nt = 0; nt < 8; nt++) {
            int row = (64 * wc + 8 * nt + g) * 132 + 8 * ks + t;
            uint32_t b0 = __float_as_uint(xj[row]);
            uint32_t b1 = __float_as_uint(xj[row + 4]);
            mma8(c[0][nt], A[0], b0, b1);
            mma8(c[1][nt], A[1], b0, b1);
        }
    }
    float lsum = 0.f;
    #pragma unroll
    for (int mt = 0; mt < 2; mt++) {
        int ir0 = i0 + 32 * wr + 16 * mt + g;
        float sqi0 = __ldg(&g_sq[b * SEQ + ir0]);
        float sqi1 = __ldg(&g_sq[b * SEQ + ir0 + 8]);
        #pragma unroll
        for (int nt = 0; nt < 8; nt++) {
            int jc = j0 + 64 * wc + 8 * nt + 2 * t;
            float sj0 = __ldg(&g_sq[b * SEQ + jc]);
            float sj1 = __ldg(&g_sq[b * SEQ + jc + 1]);
            float d00 = sqrtf(fmaxf(sqi0 + sj0 - 2.f * c[mt][nt][0], 0.f));
            float d01 = sqrtf(fmaxf(sqi0 + sj1 - 2.f * c[mt][nt][1], 0.f));
            float d10 = sqrtf(fmaxf(sqi1 + sj0 - 2.f * c[mt][nt][2], 0.f));
            float d11 = sqrtf(fmaxf(sqi1 + sj1 - 2.f * c[mt][nt][3], 0.f));
            lsum += d00 + d01 + d10 + d11;
            *(__half2*)&g_dist[(size_t)(b * SEQ + ir0) * SEQ + jc]     = __floats2half2_rn(d00, d01);
            *(__half2*)&g_dist[(size_t)(b * SEQ + ir0 + 8) * SEQ + jc] = __floats2half2_rn(d10, d11);
        }
    }
    #pragma unroll
    for (int o = 16; o; o >>= 1) lsum += __shfl_xor_sync(0xffffffffu, lsum, o);
    __shared__ float rsum[8];
    if (lane == 0) rsum[w] = lsum;
    __syncthreads();
    if (tid == 0) {
        float tot = 0.f;
        #pragma unroll
        for (int i = 0; i < 8; i++) tot += rsum[i];
        atomicAdd(&g_sum_spe, (double)tot);
    }
}

// ---------------- finalize sigmas + spatial LUT ----------------
__global__ void k_finalize() {
    int t = threadIdx.x;
    __shared__ double red[256];
    double local = 0.0;
    for (int idx = t; idx < 64 * 64; idx += 256) {
        int adx = idx >> 6, ady = idx & 63;
        double cx = adx ? 2.0 * (64 - adx) : 64.0;
        double cy = ady ? 2.0 * (64 - ady) : 64.0;
        local += cx * cy * sqrt((double)(adx * adx + ady * ady));
    }
    red[t] = local; __syncthreads();
    for (int s = 128; s; s >>= 1) { if (t < s) red[t] += red[t + s]; __syncthreads(); }
    __shared__ float inv_spa;
    if (t == 0) {
        double sig_spa = red[0] / ((double)SEQ * (double)SEQ);
        inv_spa = (float)(1.0 / (2.0 * sig_spa * sig_spa));
        double sig_spe = g_sum_spe / ((double)BATCH * (double)SEQ * (double)SEQ);
        g_inv2s2_spe = (float)(1.0 / (2.0 * sig_spe * sig_spe));
    }
    __syncthreads();
    float iv = inv_spa;
    for (int idx = t; idx < 64 * 64; idx += 256) {
        int adx = idx >> 6, ady = idx & 63;
        g_spa[idx] = expf(-sqrtf((float)(adx * adx + ady * ady)) * iv);
    }
}

// ---------------- flash attention: fp16 MMA, split-KV, 2 CTAs/SM ----------------
// smem: KH[64][136], KL[64][136], V[128][136] halves (69632 B) + WS 64x68 floats (17408 B)
#define SM_V_OFF  (2 * 64 * 136)
#define WS_BYTE_OFF (34816 * 2)
#define FLASH_SMEM_BYTES (WS_BYTE_OFF + 4352 * 4)   // 87040
__global__ void __launch_bounds__(256, 2) k_flash() {
    extern __shared__ char smraw[];
    __half* smKH = (__half*)smraw;
    __half* smKL = smKH + 64 * 136;
    __half* smV  = smKH + SM_V_OFF;
    float*  smWS = (float*)(smraw + WS_BYTE_OFF);
    int b     = blockIdx.z;
    int split = blockIdx.y;
    int i0 = blockIdx.x * 64;
    int tid = threadIdx.x;
    int lane = tid & 31, w = tid >> 5;
    int h = w >> 2, ms = w & 3;
    int g = lane >> 2, t = lane & 3;
    int hb = h * 64;
    int r0loc = 16 * ms + g;
    float inv_spe = g_inv2s2_spe;

    // ---- Q fragments: fp16 hi/lo ----
    uint32_t qh[4][4], ql[4][4];
    #pragma unroll
    for (int ks = 0; ks < 4; ks++)
        #pragma unroll
        for (int e = 0; e < 4; e++) {
            int row = i0 + r0loc + (e & 1) * 8;
            int col = hb + 16 * ks + 2 * t + (e >> 1) * 8;
            float f0 = g_q[(size_t)(b * SEQ + row) * 128 + col];
            float f1 = g_q[(size_t)(b * SEQ + row) * 128 + col + 1];
            __half2 hi2 = __floats2half2_rn(f0, f1);
            float2 back = __half22float2(hi2);
            __half2 lo2 = __floats2half2_rn(f0 - back.x, f1 - back.y);
            qh[ks][e] = *(uint32_t*)&hi2;
            ql[ks][e] = *(uint32_t*)&lo2;
        }

    float co[8][4] = {};
    float m0 = -1e30f, m1 = -1e30f, l0 = 0.f, l1 = 0.f;

    int jt_begin = split * JT_PER_SPLIT;
    for (int jt = jt_begin; jt < jt_begin + JT_PER_SPLIT; jt++) {
        int j0 = jt * 64;
        // ---- fill K hi/lo + V planes ----
        #pragma unroll
        for (int fi = tid; fi < 3072; fi += 256) {
            if (fi < 1024) {
                int r = fi >> 4, c = fi & 15;
                *(uint4*)&smKH[r * 136 + c * 8] =
                    *(const uint4*)&g_kh[(size_t)(b * SEQ + j0 + r) * 128 + c * 8];
            } else if (fi < 2048) {
                int v = fi - 1024, r = v >> 4, c = v & 15;
                *(uint4*)&smKL[r * 136 + c * 8] =
                    *(const uint4*)&g_kl[(size_t)(b * SEQ + j0 + r) * 128 + c * 8];
            } else {
                int v = fi - 2048, d = v >> 3, c = v & 7;
                *(uint4*)&smV[d * 136 + c * 8] =
                    *(const uint4*)&g_vh[(size_t)d * NTOK + b * SEQ + j0 + c * 8];
            }
        }
        // ---- mask tile ----
        int jx = j0 >> 6;
        #pragma unroll
        for (int ii = tid; ii < 2048; ii += 256) {
            int i = ii >> 5, c2 = (ii & 31) * 2;
            __half2 d2 = *(const __half2*)&g_dist[(size_t)(b * SEQ + i0 + i) * SEQ + j0 + c2];
            float2 df = __half22float2(d2);
            int gi = i0 + i;
            int adx = abs((gi >> 6) - jx);
            int gyi = gi & 63;
            const float* spaRow = &g_spa[adx * 64];
            float2 wv;
            wv.x = spaRow[abs(gyi - c2)] * __expf(-df.x * inv_spe);
            wv.y = spaRow[abs(gyi - (c2 + 1))] * __expf(-df.y * inv_spe);
            *(float2*)&smWS[i * 68 + c2] = wv;
        }
        __syncthreads();

        // ---- QK^T: fp16 2-split (hh + hl + lh) ----
        float cs[8][4] = {};
        #pragma unroll
        for (int ks = 0; ks < 4; ks++) {
            #pragma unroll
            for (int nt = 0; nt < 8; nt++) {
                int base = (8 * nt + g) * 136 + hb + 16 * ks + 2 * t;
                uint32_t kh0 = *(const uint32_t*)&smKH[base];
                uint32_t kh1 = *(const uint32_t*)&smKH[base + 8];
                uint32_t kl0 = *(const uint32_t*)&smKL[base];
                uint32_t kl1 = *(const uint32_t*)&smKL[base + 8];
                mma16(cs[nt], qh[ks], kh0, kh1);
                mma16(cs[nt], qh[ks], kl0, kl1);
                mma16(cs[nt], ql[ks], kh0, kh1);
            }
        }

        // ---- mask + online softmax (P in registers) ----
        float mloc0 = -1e30f, mloc1 = -1e30f;
        #pragma unroll
        for (int nt = 0; nt < 8; nt++) {
            int col = 8 * nt + 2 * t;
            float2 wa = *(const float2*)&smWS[r0loc * 68 + col];
            float2 wb = *(const float2*)&smWS[(r0loc + 8) * 68 + col];
            cs[nt][0] *= SCALE * wa.x; cs[nt][1] *= SCALE * wa.y;
            cs[nt][2] *= SCALE * wb.x; cs[nt][3] *= SCALE * wb.y;
            mloc0 = fmaxf(mloc0, fmaxf(cs[nt][0], cs[nt][1]));
            mloc1 = fmaxf(mloc1, fmaxf(cs[nt][2], cs[nt][3]));
        }
        #pragma unroll
        for (int o = 1; o <= 2; o <<= 1) {
            mloc0 = fmaxf(mloc0, __shfl_xor_sync(0xffffffffu, mloc0, o));
            mloc1 = fmaxf(mloc1, __shfl_xor_sync(0xffffffffu, mloc1, o));
        }
        float mn0 = fmaxf(m0, mloc0), mn1 = fmaxf(m1, mloc1);
        float corr0 = __expf(m0 - mn0), corr1 = __expf(m1 - mn1);
        m0 = mn0; m1 = mn1;
        float rs0 = 0.f, rs1 = 0.f;
        uint32_t plo[8], phi[8];
        #pragma unroll
        for (int nt = 0; nt < 8; nt++) {
            float p0 = __expf(cs[nt][0] - mn0), p1 = __expf(cs[nt][1] - mn0);
            float p2 = __expf(cs[nt][2] - mn1), p3 = __expf(cs[nt][3] - mn1);
            rs0 += p0 + p1; rs1 += p2 + p3;
            __half2 a = __floats2half2_rn(p0, p1);
            __half2 bb = __floats2half2_rn(p2, p3);
            plo[nt] = *(uint32_t*)&a;
            phi[nt] = *(uint32_t*)&bb;
        }
        #pragma unroll
        for (int o = 1; o <= 2; o <<= 1) {
            rs0 += __shfl_xor_sync(0xffffffffu, rs0, o);
            rs1 += __shfl_xor_sync(0xffffffffu, rs1, o);
        }
        l0 = l0 * corr0 + rs0;
        l1 = l1 * corr1 + rs1;
        #pragma unroll
        for (int nt = 0; nt < 8; nt++) {
            co[nt][0] *= corr0; co[nt][1] *= corr0;
            co[nt][2] *= corr1; co[nt][3] *= corr1;
        }

        // ---- PV: plain fp16 from registers ----
        #pragma unroll
        for (int ks = 0; ks < 4; ks++) {
            uint32_t pa[4] = {plo[2 * ks], phi[2 * ks], plo[2 * ks + 1], phi[2 * ks + 1]};
            #pragma unroll
            for (int nt = 0; nt < 8; nt++) {
                int base = (hb + 8 * nt + g) * 136 + 16 * ks + 2 * t;
                uint32_t b0 = *(const uint32_t*)&smV[base];
                uint32_t b1 = *(const uint32_t*)&smV[base + 8];
                mma16(co[nt], pa, b0, b1);
            }
        }
        __syncthreads();
    }

    // ---- epilogue: unnormalized partials + (m, l) ----
    int row0 = b * SEQ + i0 + r0loc;
    float* po = g_po[split];
    #pragma unroll
    for (int nt = 0; nt < 8; nt++) {
        int col = hb + 8 * nt + 2 * t;
        float2 o0 = {co[nt][0], co[nt][1]};
        float2 o1 = {co[nt][2], co[nt][3]};
        *(float2*)&po[(size_t)row0 * 128 + col] = o0;
        *(float2*)&po[(size_t)(row0 + 8) * 128 + col] = o1;
    }
    if (t == 0) {
        g_pml[split][row0 * 2 + h]       = make_float2(m0, l0);
        g_pml[split][(row0 + 8) * 2 + h] = make_float2(m1, l1);
    }
}

// ---------------- merge split-KV partials ----------------
__global__ void k_merge() {
    int idx = blockIdx.x * 256 + threadIdx.x;   // element in [0, NTOK*128)
    int row = idx >> 7, col = idx & 127;
    int h = col >> 6;
    float2 a = g_pml[0][row * 2 + h];
    float2 bb = g_pml[1][row * 2 + h];
    float M = fmaxf(a.x, bb.x);
    float ea = __expf(a.x - M), eb = __expf(bb.x - M);
    float l = ea * a.y + eb * bb.y;
    float o = (ea * g_po[0][idx] + eb * g_po[1][idx]) / l;
    g_attn[idx] = o;
}

// ---------------- launch ----------------
extern "C" void kernel_launch(void* const* d_in, const int* in_sizes, int n_in,
                              void* d_out, int out_size) {
    const float* x      = (const float*)d_in[0];
    const float* v_qkv  = (const float*)d_in[1];
    const float* g_qkv_ = (const float*)d_in[2];
    const float* b_qkv  = (const float*)d_in[3];
    const float* v_ff1  = (const float*)d_in[4];
    const float* g_ff1  = (const float*)d_in[5];
    const float* b_ff1  = (const float*)d_in[6];
    const float* v_ff2  = (const float*)d_in[7];
    const float* g_ff2  = (const float*)d_in[8];
    const float* b_ff2  = (const float*)d_in[9];
    float* out = (float*)d_out;

    const int GEMM_SMEM = 2 * 128 * 68 * 4;
    const int DIST_SMEM = 2 * 128 * 132 * 4;
    cudaFuncSetAttribute(k_gemm64, cudaFuncAttributeMaxDynamicSharedMemorySize, GEMM_SMEM);
    cudaFuncSetAttribute(k_dist,   cudaFuncAttributeMaxDynamicSharedMemorySize, DIST_SMEM);
    cudaFuncSetAttribute(k_flash,  cudaFuncAttributeMaxDynamicSharedMemorySize, FLASH_SMEM_BYTES);

    float* Wdev = nullptr;     cudaGetSymbolAddress((void**)&Wdev, g_W);
    float* attn_dev = nullptr; cudaGetSymbolAddress((void**)&attn_dev, g_attn);
    float* h1_dev = nullptr;   cudaGetSymbolAddress((void**)&h1_dev, g_q);

    k_init<<<1, 1>>>();
    k_weights<<<640, 128>>>(v_qkv, g_qkv_, v_ff1, g_ff1, v_ff2, g_ff2);
    k_sq<<<NTOK / 8, 256>>>(x);
    k_gemm64<<<dim3(6, NTOK / 64), 256, GEMM_SMEM>>>(x, Wdev, b_qkv, nullptr, 0);
    k_dist<<<dim3(32, 32, BATCH), 256, DIST_SMEM>>>(x);
    k_finalize<<<1, 256>>>();
    k_flash<<<dim3(64, NSPLIT, BATCH), 256, FLASH_SMEM_BYTES>>>();
    k_merge<<<NTOK * DIM / 256, 256>>>();
    k_gemm64<<<dim3(2, NTOK / 64), 256, GEMM_SMEM>>>(attn_dev, Wdev + 384 * 128, b_ff1, nullptr, 1);
    k_gemm64<<<dim3(2, NTOK / 64), 256, GEMM_SMEM>>>(h1_dev, Wdev + 512 * 128, b_ff2, out, 2);
}

// round 9
// speedup vs baseline: 1.0686x; 1.0686x over previous
#include <cuda_runtime.h>
#include <cuda_fp16.h>
#include <math.h>
#include <stdint.h>

#define BATCH 2
#define SEQ   4096
#define DIM   128
#define NTOK  (BATCH * SEQ)
#define SCALE 0.125f   // 64^-0.5
#define NSPLIT 2
#define JT_PER_SPLIT (64 / NSPLIT)

// ---------------- device scratch ----------------
__device__ float  g_W[640 * 128];
__device__ float  g_q[NTOK * DIM];            // reused as h1 after flash
__device__ __half g_kh[NTOK * DIM];
__device__ __half g_kl[NTOK * DIM];
__device__ __half g_vh[(size_t)DIM * NTOK];   // V fp16, transposed [d][tok]
__device__ float  g_sq[NTOK];
__device__ __half g_dist[(size_t)BATCH * SEQ * SEQ];
__device__ double g_sum_spe;
__device__ float  g_inv2s2_spe;
__device__ float  g_spa[64 * 64];
__device__ float  g_attn[NTOK * DIM];
__device__ float  g_po[NSPLIT][NTOK * DIM];   // unnormalized partial outputs
__device__ float2 g_pml[NSPLIT][NTOK * 2];    // (m, l) per row per head

// ---------------- helpers ----------------
__device__ __forceinline__ uint32_t f2tf(float f) {
    uint32_t r; asm("cvt.rna.tf32.f32 %0, %1;" : "=r"(r) : "f"(f)); return r;
}
__device__ __forceinline__ void mma8(float* c, const uint32_t* a, uint32_t b0, uint32_t b1) {
    asm volatile("mma.sync.aligned.m16n8k8.row.col.f32.tf32.tf32.f32 "
                 "{%0,%1,%2,%3},{%4,%5,%6,%7},{%8,%9},{%0,%1,%2,%3};"
                 : "+f"(c[0]), "+f"(c[1]), "+f"(c[2]), "+f"(c[3])
                 : "r"(a[0]), "r"(a[1]), "r"(a[2]), "r"(a[3]), "r"(b0), "r"(b1));
}
__device__ __forceinline__ void mma16(float* c, const uint32_t* a, uint32_t b0, uint32_t b1) {
    asm volatile("mma.sync.aligned.m16n8k16.row.col.f32.f16.f16.f32 "
                 "{%0,%1,%2,%3},{%4,%5,%6,%7},{%8,%9},{%0,%1,%2,%3};"
                 : "+f"(c[0]), "+f"(c[1]), "+f"(c[2]), "+f"(c[3])
                 : "r"(a[0]), "r"(a[1]), "r"(a[2]), "r"(a[3]), "r"(b0), "r"(b1));
}

// ---------------- init ----------------
__global__ void k_init() { g_sum_spe = 0.0; }

// ---------------- weight norm ----------------
__global__ void k_weights(const float* __restrict__ vq, const float* __restrict__ gq,
                          const float* __restrict__ v1, const float* __restrict__ g1,
                          const float* __restrict__ v2, const float* __restrict__ g2) {
    int r = blockIdx.x, t = threadIdx.x;
    const float* v; float g;
    if (r < 384)      { v = vq + r * 128;        g = gq[r]; }
    else if (r < 512) { v = v1 + (r - 384) * 128; g = g1[r - 384]; }
    else              { v = v2 + (r - 512) * 128; g = g2[r - 512]; }
    float val = v[t];
    float ss = val * val;
    #pragma unroll
    for (int o = 16; o; o >>= 1) ss += __shfl_xor_sync(0xffffffffu, ss, o);
    __shared__ float ws[4];
    if ((t & 31) == 0) ws[t >> 5] = ss;
    __syncthreads();
    float tot = ws[0] + ws[1] + ws[2] + ws[3];
    g_W[r * 128 + t] = val * (g / sqrtf(tot));
}

// ---------------- per-token ||x||^2 ----------------
__global__ void k_sq(const float* __restrict__ x) {
    int token = blockIdx.x * 8 + (threadIdx.x >> 5);
    int lane  = threadIdx.x & 31;
    const float4* xp = (const float4*)(x + token * 128);
    float4 a = xp[lane];
    float ss = a.x * a.x + a.y * a.y + a.z * a.z + a.w * a.w;
    #pragma unroll
    for (int o = 16; o; o >>= 1) ss += __shfl_xor_sync(0xffffffffu, ss, o);
    if (lane == 0) g_sq[token] = ss;
}

// ---------------- tiled projection GEMM (scalar fp32, exact) ----------------
__global__ void __launch_bounds__(256) k_gemm64(const float* __restrict__ A,
                                                const float* __restrict__ Wrows,
                                                const float* __restrict__ bias,
                                                float* __restrict__ out, int mode) {
    extern __shared__ float sm[];
    float* aT = sm;
    float* wT = sm + 128 * 68;
    int c0 = blockIdx.x * 64;
    int t0 = blockIdx.y * 64;
    int tid = threadIdx.x;
    for (int idx = tid; idx < 64 * 128; idx += 256) {
        int r = idx >> 7, k = idx & 127;
        aT[k * 68 + r] = A[(t0 + r) * 128 + k];
        wT[k * 68 + r] = Wrows[(c0 + r) * 128 + k];
    }
    __syncthreads();
    int ty = tid >> 4, tx = tid & 15;
    float acc[4][4] = {};
    #pragma unroll 4
    for (int k = 0; k < 128; k++) {
        float4 av = *(const float4*)&aT[k * 68 + 4 * ty];
        float4 bv = *(const float4*)&wT[k * 68 + 4 * tx];
        float a[4] = {av.x, av.y, av.z, av.w};
        float c[4] = {bv.x, bv.y, bv.z, bv.w};
        #pragma unroll
        for (int i = 0; i < 4; i++)
            #pragma unroll
            for (int j = 0; j < 4; j++) acc[i][j] = fmaf(a[i], c[j], acc[i][j]);
    }
    #pragma unroll
    for (int i = 0; i < 4; i++) {
        int token = t0 + 4 * ty + i;
        #pragma unroll
        for (int j = 0; j < 4; j++) {
            int c = c0 + 4 * tx + j;
            float val = acc[i][j] + __ldg(&bias[c]);
            if (mode == 0) {
                if (c < 128) {
                    g_q[token * 128 + c] = val;
                } else if (c < 256) {
                    int d = c - 128;
                    __half hi = __float2half_rn(val);
                    __half lo = __float2half_rn(val - __half2float(hi));
                    g_kh[token * 128 + d] = hi;
                    g_kl[token * 128 + d] = lo;
                } else {
                    int d = c - 256;
                    g_vh[(size_t)d * NTOK + token] = __float2half_rn(val);
                }
            } else if (mode == 1) {
                g_q[token * 128 + c] = 0.5f * val * (1.0f + erff(val * 0.70710678118654752f));
            } else {
                out[token * 128 + c] = val;
            }
        }
    }
}

// ---------------- pairwise distance via tf32 MMA ----------------
__global__ void __launch_bounds__(256) k_dist(const float* __restrict__ x) {
    extern __shared__ float sm[];
    float* xi = sm;              // [128][132], tf32-rounded
    float* xj = sm + 128 * 132;
    int b = blockIdx.z, i0 = blockIdx.y * 128, j0 = blockIdx.x * 128;
    int tid = threadIdx.x;
    for (int fi = tid; fi < 4096; fi += 256) {
        int r = fi >> 5, c4 = (fi & 31) * 4;
        float4 a = *(const float4*)&x[(size_t)(b * SEQ + i0 + r) * 128 + c4];
        float4 bb = *(const float4*)&x[(size_t)(b * SEQ + j0 + r) * 128 + c4];
        a.x = __uint_as_float(f2tf(a.x)); a.y = __uint_as_float(f2tf(a.y));
        a.z = __uint_as_float(f2tf(a.z)); a.w = __uint_as_float(f2tf(a.w));
        bb.x = __uint_as_float(f2tf(bb.x)); bb.y = __uint_as_float(f2tf(bb.y));
        bb.z = __uint_as_float(f2tf(bb.z)); bb.w = __uint_as_float(f2tf(bb.w));
        *(float4*)&xi[r * 132 + c4] = a;
        *(float4*)&xj[r * 132 + c4] = bb;
    }
    __syncthreads();
    int lane = tid & 31, w = tid >> 5;
    int wr = w >> 1, wc = w & 1;
    int g = lane >> 2, t = lane & 3;
    float c[2][8][4] = {};
    #pragma unroll 1
    for (int ks = 0; ks < 16; ks++) {
        uint32_t A[2][4];
        #pragma unroll
        for (int mt = 0; mt < 2; mt++)
            #pragma unroll
            for (int e = 0; e < 4; e++)
                A[mt][e] = __float_as_uint(xi[(32 * wr + 16 * mt + g + 8 * (e & 1)) * 132 + 8 * ks + t + 4 * (e >> 1)]);
        #pragma unroll
        for (int nt = 0; nt < 8; nt++) {
            int row = (64 * wc + 8 * nt + g) * 132 + 8 * ks + t;
            uint32_t b0 = __float_as_uint(xj[row]);
            uint32_t b1 = __float_as_uint(xj[row + 4]);
            mma8(c[0][nt], A[0], b0, b1);
            mma8(c[1][nt], A[1], b0, b1);
        }
    }
    float lsum = 0.f;
    #pragma unroll
    for (int mt = 0; mt < 2; mt++) {
        int ir0 = i0 + 32 * wr + 16 * mt + g;
        float sqi0 = __ldg(&g_sq[b * SEQ + ir0]);
        float sqi1 = __ldg(&g_sq[b * SEQ + ir0 + 8]);
        #pragma unroll
        for (int nt = 0; nt < 8; nt++) {
            int jc = j0 + 64 * wc + 8 * nt + 2 * t;
            float sj0 = __ldg(&g_sq[b * SEQ + jc]);
            float sj1 = __ldg(&g_sq[b * SEQ + jc + 1]);
            float d00 = sqrtf(fmaxf(sqi0 + sj0 - 2.f * c[mt][nt][0], 0.f));
            float d01 = sqrtf(fmaxf(sqi0 + sj1 - 2.f * c[mt][nt][1], 0.f));
            float d10 = sqrtf(fmaxf(sqi1 + sj0 - 2.f * c[mt][nt][2], 0.f));
            float d11 = sqrtf(fmaxf(sqi1 + sj1 - 2.f * c[mt][nt][3], 0.f));
            lsum += d00 + d01 + d10 + d11;
            *(__half2*)&g_dist[(size_t)(b * SEQ + ir0) * SEQ + jc]     = __floats2half2_rn(d00, d01);
            *(__half2*)&g_dist[(size_t)(b * SEQ + ir0 + 8) * SEQ + jc] = __floats2half2_rn(d10, d11);
        }
    }
    #pragma unroll
    for (int o = 16; o; o >>= 1) lsum += __shfl_xor_sync(0xffffffffu, lsum, o);
    __shared__ float rsum[8];
    if (lane == 0) rsum[w] = lsum;
    __syncthreads();
    if (tid == 0) {
        float tot = 0.f;
        #pragma unroll
        for (int i = 0; i < 8; i++) tot += rsum[i];
        atomicAdd(&g_sum_spe, (double)tot);
    }
}

// ---------------- finalize sigmas + spatial LUT ----------------
__global__ void k_finalize() {
    int t = threadIdx.x;
    __shared__ double red[256];
    double local = 0.0;
    for (int idx = t; idx < 64 * 64; idx += 256) {
        int adx = idx >> 6, ady = idx & 63;
        double cx = adx ? 2.0 * (64 - adx) : 64.0;
        double cy = ady ? 2.0 * (64 - ady) : 64.0;
        local += cx * cy * sqrt((double)(adx * adx + ady * ady));
    }
    red[t] = local; __syncthreads();
    for (int s = 128; s; s >>= 1) { if (t < s) red[t] += red[t + s]; __syncthreads(); }
    __shared__ float inv_spa;
    if (t == 0) {
        double sig_spa = red[0] / ((double)SEQ * (double)SEQ);
        inv_spa = (float)(1.0 / (2.0 * sig_spa * sig_spa));
        double sig_spe = g_sum_spe / ((double)BATCH * (double)SEQ * (double)SEQ);
        g_inv2s2_spe = (float)(1.0 / (2.0 * sig_spe * sig_spe));
    }
    __syncthreads();
    float iv = inv_spa;
    for (int idx = t; idx < 64 * 64; idx += 256) {
        int adx = idx >> 6, ady = idx & 63;
        g_spa[idx] = expf(-sqrtf((float)(adx * adx + ady * ady)) * iv);
    }
}

// ---------------- flash attention: M=128 tile, fp16 MMA 2-term QK, split-KV ----------------
// smem: KH[64][136], KL[64][136], V[128][136] halves (69632 B) + WS[128][68] floats (34816 B)
#define WS_BYTE_OFF 69632
#define FLASH_SMEM_BYTES (WS_BYTE_OFF + 128 * 68 * 4)   // 104448
__global__ void __launch_bounds__(256, 1) k_flash() {
    extern __shared__ char smraw[];
    __half* smKH = (__half*)smraw;
    __half* smKL = smKH + 64 * 136;
    __half* smV  = smKH + 2 * 64 * 136;
    float*  smWS = (float*)(smraw + WS_BYTE_OFF);
    int b     = blockIdx.z;
    int split = blockIdx.y;
    int i0 = blockIdx.x * 128;
    int tid = threadIdx.x;
    int lane = tid & 31, w = tid >> 5;
    int h = w >> 2, mq = w & 3;
    int g = lane >> 2, t = lane & 3;
    int hb = h * 64;
    int rbase = 32 * mq;                 // local row base of this warp (covers 32 rows)
    float inv_spe = g_inv2s2_spe;

    // ---- Q fragments: fp16 hi only (2-term QK uses qh with kh and kl) ----
    uint32_t qh[2][4][4];
    #pragma unroll
    for (int m = 0; m < 2; m++)
        #pragma unroll
        for (int ks = 0; ks < 4; ks++)
            #pragma unroll
            for (int e = 0; e < 4; e++) {
                int row = i0 + rbase + 16 * m + g + (e & 1) * 8;
                int col = hb + 16 * ks + 2 * t + (e >> 1) * 8;
                float f0 = g_q[(size_t)(b * SEQ + row) * 128 + col];
                float f1 = g_q[(size_t)(b * SEQ + row) * 128 + col + 1];
                __half2 hi2 = __floats2half2_rn(f0, f1);
                qh[m][ks][e] = *(uint32_t*)&hi2;
            }

    float co[2][8][4] = {};
    float mA[2] = {-1e30f, -1e30f}, mB[2] = {-1e30f, -1e30f};
    float lA[2] = {0.f, 0.f},       lB[2] = {0.f, 0.f};

    int jt_begin = split * JT_PER_SPLIT;
    for (int jt = jt_begin; jt < jt_begin + JT_PER_SPLIT; jt++) {
        int j0 = jt * 64;
        // ---- fill K hi/lo + V planes ----
        #pragma unroll
        for (int fi = tid; fi < 3072; fi += 256) {
            if (fi < 1024) {
                int r = fi >> 4, c = fi & 15;
                *(uint4*)&smKH[r * 136 + c * 8] =
                    *(const uint4*)&g_kh[(size_t)(b * SEQ + j0 + r) * 128 + c * 8];
            } else if (fi < 2048) {
                int v = fi - 1024, r = v >> 4, c = v & 15;
                *(uint4*)&smKL[r * 136 + c * 8] =
                    *(const uint4*)&g_kl[(size_t)(b * SEQ + j0 + r) * 128 + c * 8];
            } else {
                int v = fi - 2048, d = v >> 3, c = v & 7;
                *(uint4*)&smV[d * 136 + c * 8] =
                    *(const uint4*)&g_vh[(size_t)d * NTOK + b * SEQ + j0 + c * 8];
            }
        }
        // ---- mask tile (128 rows x 64 cols) ----
        int jx = j0 >> 6;
        #pragma unroll
        for (int ii = tid; ii < 4096; ii += 256) {
            int i = ii >> 5, c2 = (ii & 31) * 2;
            __half2 d2 = *(const __half2*)&g_dist[(size_t)(b * SEQ + i0 + i) * SEQ + j0 + c2];
            float2 df = __half22float2(d2);
            int gi = i0 + i;
            int adx = abs((gi >> 6) - jx);
            int gyi = gi & 63;
            const float* spaRow = &g_spa[adx * 64];
            float2 wv;
            wv.x = spaRow[abs(gyi - c2)] * __expf(-df.x * inv_spe);
            wv.y = spaRow[abs(gyi - (c2 + 1))] * __expf(-df.y * inv_spe);
            *(float2*)&smWS[i * 68 + c2] = wv;
        }
        __syncthreads();

        uint32_t plo[2][8], phi[2][8];
        #pragma unroll
        for (int m = 0; m < 2; m++) {
            int r0 = rbase + 16 * m + g;
            // ---- QK^T: 2-term fp16 (qh*kh + qh*kl), K frags shared across nothing here
            float cs[8][4] = {};
            #pragma unroll
            for (int ks = 0; ks < 4; ks++) {
                #pragma unroll
                for (int nt = 0; nt < 8; nt++) {
                    int base = (8 * nt + g) * 136 + hb + 16 * ks + 2 * t;
                    uint32_t kh0 = *(const uint32_t*)&smKH[base];
                    uint32_t kh1 = *(const uint32_t*)&smKH[base + 8];
                    uint32_t kl0 = *(const uint32_t*)&smKL[base];
                    uint32_t kl1 = *(const uint32_t*)&smKL[base + 8];
                    mma16(cs[nt], qh[m][ks], kh0, kh1);
                    mma16(cs[nt], qh[m][ks], kl0, kl1);
                }
            }
            // ---- mask + online softmax ----
            float mloc0 = -1e30f, mloc1 = -1e30f;
            #pragma unroll
            for (int nt = 0; nt < 8; nt++) {
                int col = 8 * nt + 2 * t;
                float2 wa = *(const float2*)&smWS[r0 * 68 + col];
                float2 wb = *(const float2*)&smWS[(r0 + 8) * 68 + col];
                cs[nt][0] *= SCALE * wa.x; cs[nt][1] *= SCALE * wa.y;
                cs[nt][2] *= SCALE * wb.x; cs[nt][3] *= SCALE * wb.y;
                mloc0 = fmaxf(mloc0, fmaxf(cs[nt][0], cs[nt][1]));
                mloc1 = fmaxf(mloc1, fmaxf(cs[nt][2], cs[nt][3]));
            }
            #pragma unroll
            for (int o = 1; o <= 2; o <<= 1) {
                mloc0 = fmaxf(mloc0, __shfl_xor_sync(0xffffffffu, mloc0, o));
                mloc1 = fmaxf(mloc1, __shfl_xor_sync(0xffffffffu, mloc1, o));
            }
            float mn0 = fmaxf(mA[m], mloc0), mn1 = fmaxf(mB[m], mloc1);
            float corr0 = __expf(mA[m] - mn0), corr1 = __expf(mB[m] - mn1);
            mA[m] = mn0; mB[m] = mn1;
            float rs0 = 0.f, rs1 = 0.f;
            #pragma unroll
            for (int nt = 0; nt < 8; nt++) {
                float p0 = __expf(cs[nt][0] - mn0), p1 = __expf(cs[nt][1] - mn0);
                float p2 = __expf(cs[nt][2] - mn1), p3 = __expf(cs[nt][3] - mn1);
                rs0 += p0 + p1; rs1 += p2 + p3;
                __half2 a = __floats2half2_rn(p0, p1);
                __half2 bb = __floats2half2_rn(p2, p3);
                plo[m][nt] = *(uint32_t*)&a;
                phi[m][nt] = *(uint32_t*)&bb;
            }
            #pragma unroll
            for (int o = 1; o <= 2; o <<= 1) {
                rs0 += __shfl_xor_sync(0xffffffffu, rs0, o);
                rs1 += __shfl_xor_sync(0xffffffffu, rs1, o);
            }
            lA[m] = lA[m] * corr0 + rs0;
            lB[m] = lB[m] * corr1 + rs1;
            #pragma unroll
            for (int nt = 0; nt < 8; nt++) {
                co[m][nt][0] *= corr0; co[m][nt][1] *= corr0;
                co[m][nt][2] *= corr1; co[m][nt][3] *= corr1;
            }
        }

        // ---- PV: plain fp16, V frags shared across both m ----
        #pragma unroll
        for (int ks = 0; ks < 4; ks++) {
            uint32_t pa0[4] = {plo[0][2 * ks], phi[0][2 * ks], plo[0][2 * ks + 1], phi[0][2 * ks + 1]};
            uint32_t pa1[4] = {plo[1][2 * ks], phi[1][2 * ks], plo[1][2 * ks + 1], phi[1][2 * ks + 1]};
            #pragma unroll
            for (int nt = 0; nt < 8; nt++) {
                int base = (hb + 8 * nt + g) * 136 + 16 * ks + 2 * t;
                uint32_t b0 = *(const uint32_t*)&smV[base];
                uint32_t b1 = *(const uint32_t*)&smV[base + 8];
                mma16(co[0][nt], pa0, b0, b1);
                mma16(co[1][nt], pa1, b0, b1);
            }
        }
        __syncthreads();
    }

    // ---- epilogue: unnormalized partials + (m, l) ----
    float* po = g_po[split];
    #pragma unroll
    for (int m = 0; m < 2; m++) {
        int row0 = b * SEQ + i0 + rbase + 16 * m + g;
        #pragma unroll
        for (int nt = 0; nt < 8; nt++) {
            int col = hb + 8 * nt + 2 * t;
            float2 o0 = {co[m][nt][0], co[m][nt][1]};
            float2 o1 = {co[m][nt][2], co[m][nt][3]};
            *(float2*)&po[(size_t)row0 * 128 + col] = o0;
            *(float2*)&po[(size_t)(row0 + 8) * 128 + col] = o1;
        }
        if (t == 0) {
            g_pml[split][row0 * 2 + h]       = make_float2(mA[m], lA[m]);
            g_pml[split][(row0 + 8) * 2 + h] = make_float2(mB[m], lB[m]);
        }
    }
}

// ---------------- merge split-KV partials ----------------
__global__ void k_merge() {
    int idx = blockIdx.x * 256 + threadIdx.x;
    int row = idx >> 7, col = idx & 127;
    int h = col >> 6;
    float2 a = g_pml[0][row * 2 + h];
    float2 bb = g_pml[1][row * 2 + h];
    float M = fmaxf(a.x, bb.x);
    float ea = __expf(a.x - M), eb = __expf(bb.x - M);
    float l = ea * a.y + eb * bb.y;
    float o = (ea * g_po[0][idx] + eb * g_po[1][idx]) / l;
    g_attn[idx] = o;
}

// ---------------- launch ----------------
extern "C" void kernel_launch(void* const* d_in, const int* in_sizes, int n_in,
                              void* d_out, int out_size) {
    const float* x      = (const float*)d_in[0];
    const float* v_qkv  = (const float*)d_in[1];
    const float* g_qkv_ = (const float*)d_in[2];
    const float* b_qkv  = (const float*)d_in[3];
    const float* v_ff1  = (const float*)d_in[4];
    const float* g_ff1  = (const float*)d_in[5];
    const float* b_ff1  = (const float*)d_in[6];
    const float* v_ff2  = (const float*)d_in[7];
    const float* g_ff2  = (const float*)d_in[8];
    const float* b_ff2  = (const float*)d_in[9];
    float* out = (float*)d_out;

    const int GEMM_SMEM = 2 * 128 * 68 * 4;
    const int DIST_SMEM = 2 * 128 * 132 * 4;
    cudaFuncSetAttribute(k_gemm64, cudaFuncAttributeMaxDynamicSharedMemorySize, GEMM_SMEM);
    cudaFuncSetAttribute(k_dist,   cudaFuncAttributeMaxDynamicSharedMemorySize, DIST_SMEM);
    cudaFuncSetAttribute(k_flash,  cudaFuncAttributeMaxDynamicSharedMemorySize, FLASH_SMEM_BYTES);

    float* Wdev = nullptr;     cudaGetSymbolAddress((void**)&Wdev, g_W);
    float* attn_dev = nullptr; cudaGetSymbolAddress((void**)&attn_dev, g_attn);
    float* h1_dev = nullptr;   cudaGetSymbolAddress((void**)&h1_dev, g_q);

    k_init<<<1, 1>>>();
    k_weights<<<640, 128>>>(v_qkv, g_qkv_, v_ff1, g_ff1, v_ff2, g_ff2);
    k_sq<<<NTOK / 8, 256>>>(x);
    k_gemm64<<<dim3(6, NTOK / 64), 256, GEMM_SMEM>>>(x, Wdev, b_qkv, nullptr, 0);
    k_dist<<<dim3(32, 32, BATCH), 256, DIST_SMEM>>>(x);
    k_finalize<<<1, 256>>>();
    k_flash<<<dim3(SEQ / 128, NSPLIT, BATCH), 256, FLASH_SMEM_BYTES>>>();
    k_merge<<<NTOK * DIM / 256, 256>>>();
    k_gemm64<<<dim3(2, NTOK / 64), 256, GEMM_SMEM>>>(attn_dev, Wdev + 384 * 128, b_ff1, nullptr, 1);
    k_gemm64<<<dim3(2, NTOK / 64), 256, GEMM_SMEM>>>(h1_dev, Wdev + 512 * 128, b_ff2, out, 2);
}